// round 2
// baseline (speedup 1.0000x reference)
#include <cuda_runtime.h>
#include <cuda_bf16.h>

#define Nn   100000
#define Ee   1600000
#define DIN  256
#define DH   128
#define DOUT 8
#define HOPS 5

// ---------------- scratch (static device globals; no allocation) ----------------
__device__ float g_xp[Nn * DH];            // relu(x_paper @ W1_paper + b1)
__device__ float g_xa[Nn * DH];
__device__ float g_hp[2][Nn * DH];         // double-buffered paper hidden
__device__ float g_ha[2][Nn * DH];         // double-buffered author hidden
__device__ int   g_cols[4][Ee];            // CSR-sorted cols per edge type
__device__ float g_vals[4][Ee];            // CSR-sorted vals per edge type
__device__ int   g_rowptr[4][Nn + 1];
__device__ int   g_deg[4][Nn];
__device__ int   g_cur[4][Nn];
__device__ float g_w[HOPS * 4];            // softmaxed layer weights

// buffer selector for kernels (host can't take &__device__ array without symbol API)
__device__ __forceinline__ float* pick_buf(int s) {
    switch (s) {
        case 0: return g_xp;
        case 1: return g_xa;
        case 2: return g_hp[0];
        case 3: return g_hp[1];
        case 4: return g_ha[0];
        default: return g_ha[1];
    }
}

// ---------------- CSR build ----------------
__global__ void zero_deg_kernel() {
    int i = blockIdx.x * blockDim.x + threadIdx.x;
    if (i < 4 * Nn) ((int*)g_deg)[i] = 0;
}

__global__ void hist_kernel(const int* __restrict__ r0, const int* __restrict__ r1,
                            const int* __restrict__ r2, const int* __restrict__ r3) {
    int i = blockIdx.x * blockDim.x + threadIdx.x;
    int et = blockIdx.y;
    if (i >= Ee) return;
    const int* r = (et == 0) ? r0 : (et == 1) ? r1 : (et == 2) ? r2 : r3;
    atomicAdd(&g_deg[et][r[i]], 1);
}

__global__ void scan_kernel() {
    // one block per edge type, 1024 threads, chunked exclusive scan over N
    const int et = blockIdx.x;
    const int t  = threadIdx.x;
    const int CH = (Nn + 1023) / 1024;   // 98
    int base = t * CH;
    int lsum = 0;
    for (int j = 0; j < CH; j++) {
        int idx = base + j;
        if (idx < Nn) lsum += g_deg[et][idx];
    }
    __shared__ int ssum[1024];
    ssum[t] = lsum;
    __syncthreads();
    for (int off = 1; off < 1024; off <<= 1) {
        int v = 0;
        if (t >= off) v = ssum[t - off];
        __syncthreads();
        ssum[t] += v;
        __syncthreads();
    }
    int run = (t == 0) ? 0 : ssum[t - 1];   // exclusive prefix of this chunk
    for (int j = 0; j < CH; j++) {
        int idx = base + j;
        if (idx < Nn) {
            g_rowptr[et][idx] = run;
            g_cur[et][idx]    = run;
            run += g_deg[et][idx];
        }
    }
    if (t == 1023) g_rowptr[et][Nn] = ssum[1023];
}

__global__ void scatter_kernel(const int* __restrict__ r0, const int* __restrict__ r1,
                               const int* __restrict__ r2, const int* __restrict__ r3,
                               const int* __restrict__ c0, const int* __restrict__ c1,
                               const int* __restrict__ c2, const int* __restrict__ c3,
                               const float* __restrict__ v0, const float* __restrict__ v1,
                               const float* __restrict__ v2, const float* __restrict__ v3) {
    int i = blockIdx.x * blockDim.x + threadIdx.x;
    int et = blockIdx.y;
    if (i >= Ee) return;
    const int*   r = (et == 0) ? r0 : (et == 1) ? r1 : (et == 2) ? r2 : r3;
    const int*   c = (et == 0) ? c0 : (et == 1) ? c1 : (et == 2) ? c2 : c3;
    const float* v = (et == 0) ? v0 : (et == 1) ? v1 : (et == 2) ? v2 : v3;
    int row = r[i];
    int p = atomicAdd(&g_cur[et][row], 1);
    g_cols[et][p] = c[i];
    g_vals[et][p] = v[i];
}

// ---------------- layer-weight softmax ----------------
__global__ void wsoft_kernel(const float* __restrict__ lw) {
    int i = threadIdx.x;
    if (i < HOPS) {
        #pragma unroll
        for (int p = 0; p < 4; p += 2) {
            float a = lw[i * 4 + p], b = lw[i * 4 + p + 1];
            float m = fmaxf(a, b);
            float ea = expf(a - m), eb = expf(b - m);
            float inv = 1.0f / (ea + eb);
            g_w[i * 4 + p]     = ea * inv;
            g_w[i * 4 + p + 1] = eb * inv;
        }
    }
}

// ---------------- input projection: relu(X @ W1 + b1) -> xbuf and hbuf ----------------
// block: 128 threads (one output column each), 32 rows per block
__global__ void __launch_bounds__(128, 4)
proj_kernel(const float* __restrict__ X, const float* __restrict__ W,
            const float* __restrict__ b, int which /*0 paper, 1 author*/) {
    __shared__ float4 sx[32][DIN / 4];   // 32 KB
    const int tid = threadIdx.x;
    const int row0 = blockIdx.x * 32;
    // cooperative load of 32 input rows
    const float4* X4 = (const float4*)X;
    for (int i = tid; i < 32 * (DIN / 4); i += 128) {
        int r = i / (DIN / 4), k4 = i % (DIN / 4);
        sx[r][k4] = X4[(size_t)(row0 + r) * (DIN / 4) + k4];
    }
    __syncthreads();

    const int j = tid;           // output column [0,128)
    float acc[32];
    #pragma unroll
    for (int r = 0; r < 32; r++) acc[r] = 0.0f;

    #pragma unroll 4
    for (int k4 = 0; k4 < DIN / 4; k4++) {
        float wa = W[(k4 * 4 + 0) * DH + j];
        float wb = W[(k4 * 4 + 1) * DH + j];
        float wc = W[(k4 * 4 + 2) * DH + j];
        float wd = W[(k4 * 4 + 3) * DH + j];
        #pragma unroll
        for (int r = 0; r < 32; r++) {
            float4 x = sx[r][k4];
            acc[r] += x.x * wa;
            acc[r] += x.y * wb;
            acc[r] += x.z * wc;
            acc[r] += x.w * wd;
        }
    }
    float bias = b[j];
    float* xbuf = which ? g_xa : g_xp;
    float* hbuf = which ? g_ha[0] : g_hp[0];
    #pragma unroll
    for (int r = 0; r < 32; r++) {
        float v = fmaxf(acc[r] + bias, 0.0f);
        size_t o = (size_t)(row0 + r) * DH + j;
        xbuf[o] = v;
        hbuf[o] = v;
    }
}

// ---------------- fused node-type update ----------------
// dst = w0*(spmm(et0, hA) + diag0*xs) + w1*(spmm(et1, hB) + diag1*xs)
// warp per row; lane handles 4 features (float4); 2-deep (col,val) prefetch
__global__ void __launch_bounds__(256)
update_kernel(int et0, int et1,
              int selA, int selB, int selX, int selD,
              const float* __restrict__ diag0,
              const float* __restrict__ diag1,
              int widx) {
    int gw = (blockIdx.x * blockDim.x + threadIdx.x) >> 5;
    if (gw >= Nn) return;
    const int lane = threadIdx.x & 31;
    const int row = gw;

    const float4* __restrict__ hA4 = (const float4*)pick_buf(selA);
    const float4* __restrict__ hB4 = (const float4*)pick_buf(selB);
    const float4* __restrict__ xs4 = (const float4*)pick_buf(selX);
    float4* dst4 = (float4*)pick_buf(selD);

    const float w0 = g_w[widx], w1 = g_w[widx + 1];

    float4 a0 = make_float4(0.f, 0.f, 0.f, 0.f);
    float4 a1 = make_float4(0.f, 0.f, 0.f, 0.f);

    {
        const int s = g_rowptr[et0][row], e = g_rowptr[et0][row + 1];
        int   nc = (s < e) ? g_cols[et0][s] : 0;
        float nv = (s < e) ? g_vals[et0][s] : 0.f;
        for (int i = s; i < e; i++) {
            int c = nc; float v = nv;
            if (i + 1 < e) { nc = g_cols[et0][i + 1]; nv = g_vals[et0][i + 1]; }
            float4 h = hA4[(size_t)c * (DH / 4) + lane];
            a0.x += v * h.x; a0.y += v * h.y; a0.z += v * h.z; a0.w += v * h.w;
        }
    }
    {
        const int s = g_rowptr[et1][row], e = g_rowptr[et1][row + 1];
        int   nc = (s < e) ? g_cols[et1][s] : 0;
        float nv = (s < e) ? g_vals[et1][s] : 0.f;
        for (int i = s; i < e; i++) {
            int c = nc; float v = nv;
            if (i + 1 < e) { nc = g_cols[et1][i + 1]; nv = g_vals[et1][i + 1]; }
            float4 h = hB4[(size_t)c * (DH / 4) + lane];
            a1.x += v * h.x; a1.y += v * h.y; a1.z += v * h.z; a1.w += v * h.w;
        }
    }

    float4 xv = xs4[(size_t)row * (DH / 4) + lane];
    float dd = w0 * diag0[row] + w1 * diag1[row];
    float4 r;
    r.x = w0 * a0.x + w1 * a1.x + dd * xv.x;
    r.y = w0 * a0.y + w1 * a1.y + dd * xv.y;
    r.z = w0 * a0.z + w1 * a1.z + dd * xv.z;
    r.w = w0 * a0.w + w1 * a1.w + dd * xv.w;
    dst4[(size_t)row * (DH / 4) + lane] = r;
}

// ---------------- final projection: h_p @ W2 + b2 ----------------
__global__ void final_kernel(const float* __restrict__ W2, const float* __restrict__ b2,
                             float* __restrict__ out) {
    __shared__ float sW[DH * DOUT];      // 4 KB
    __shared__ float sh[32 * DH];        // 16 KB
    const int tid = threadIdx.x;
    for (int i = tid; i < DH * DOUT; i += 256) sW[i] = W2[i];
    const int row0 = blockIdx.x * 32;
    const float4* src = (const float4*)(g_hp[HOPS & 1]);
    float4* sh4 = (float4*)sh;
    for (int i = tid; i < 32 * (DH / 4); i += 256)
        sh4[i] = src[(size_t)row0 * (DH / 4) + i];
    __syncthreads();

    const int r = tid >> 3, oc = tid & 7;
    float acc = b2[oc];
    #pragma unroll 8
    for (int k = 0; k < DH; k++)
        acc += sh[r * DH + k] * sW[k * DOUT + oc];
    out[(size_t)(row0 + r) * DOUT + oc] = acc;
}

// ---------------- launch ----------------
extern "C" void kernel_launch(void* const* d_in, const int* in_sizes, int n_in,
                              void* d_out, int out_size) {
    const float* x_paper  = (const float*)d_in[0];
    const float* x_author = (const float*)d_in[1];
    const int*   rows[4];
    const int*   cols[4];
    const float* vals[4];
    const float* diag[4];
    for (int t = 0; t < 4; t++) {
        int base = 2 + t * 4;
        rows[t] = (const int*)d_in[base + 0];
        cols[t] = (const int*)d_in[base + 1];
        vals[t] = (const float*)d_in[base + 2];
        diag[t] = (const float*)d_in[base + 3];
    }
    const float* W1p = (const float*)d_in[18];
    const float* b1p = (const float*)d_in[19];
    const float* W1a = (const float*)d_in[20];
    const float* b1a = (const float*)d_in[21];
    const float* W2  = (const float*)d_in[22];
    const float* b2  = (const float*)d_in[23];
    const float* lw  = (const float*)d_in[24];
    float* out = (float*)d_out;

    // CSR build
    zero_deg_kernel<<<(4 * Nn + 255) / 256, 256>>>();
    hist_kernel<<<dim3((Ee + 255) / 256, 4), 256>>>(rows[0], rows[1], rows[2], rows[3]);
    scan_kernel<<<4, 1024>>>();
    scatter_kernel<<<dim3((Ee + 255) / 256, 4), 256>>>(
        rows[0], rows[1], rows[2], rows[3],
        cols[0], cols[1], cols[2], cols[3],
        vals[0], vals[1], vals[2], vals[3]);

    // layer weights
    wsoft_kernel<<<1, 32>>>(lw);

    // input projections (N = 3125 * 32 exactly)
    proj_kernel<<<Nn / 32, 128>>>(x_paper, W1p, b1p, 0);
    proj_kernel<<<Nn / 32, 128>>>(x_author, W1a, b1a, 1);

    // selectors: 0=g_xp 1=g_xa 2=g_hp[0] 3=g_hp[1] 4=g_ha[0] 5=g_ha[1]
    const int grid_u = (Nn * 32) / 256;   // 12500
    for (int i = 0; i < HOPS; i++) {
        int a = i & 1, bnew = (i + 1) & 1;
        // paper: pp gathers h_p[a], pa gathers h_a[a], writes h_p[bnew]
        update_kernel<<<grid_u, 256>>>(0, 1, 2 + a, 4 + a, 0, 2 + bnew,
                                       diag[0], diag[1], i * 4);
        // author: ap gathers FRESH h_p[bnew], aa gathers h_a[a], writes h_a[bnew]
        update_kernel<<<grid_u, 256>>>(2, 3, 2 + bnew, 4 + a, 1, 4 + bnew,
                                       diag[2], diag[3], i * 4 + 2);
    }

    // output projection (reads g_hp[HOPS&1] = g_hp[1])
    final_kernel<<<Nn / 32, 256>>>(W2, b2, out);
}

// round 3
// speedup vs baseline: 1.1481x; 1.1481x over previous
#include <cuda_runtime.h>
#include <cuda_bf16.h>

#define Nn   100000
#define Ee   1600000
#define DIN  256
#define DH   128
#define DOUT 8
#define HOPS 5

// ---------------- scratch (static device globals; no allocation) ----------------
__device__ float g_xp[Nn * DH];            // relu(x_paper @ W1_paper + b1)
__device__ float g_xa[Nn * DH];
__device__ float g_hp[2][Nn * DH];         // double-buffered paper hidden
__device__ float g_ha[2][Nn * DH];         // double-buffered author hidden
__device__ int2  g_cv[4][Ee];              // CSR-sorted (col, val-as-int) per edge type
__device__ int   g_rowptr[4][Nn + 1];
__device__ int   g_deg[4][Nn];
__device__ int   g_cur[4][Nn];
__device__ float g_w[HOPS * 4];            // softmaxed layer weights

__device__ __forceinline__ float* pick_buf(int s) {
    switch (s) {
        case 0: return g_xp;
        case 1: return g_xa;
        case 2: return g_hp[0];
        case 3: return g_hp[1];
        case 4: return g_ha[0];
        default: return g_ha[1];
    }
}

// ---------------- CSR build ----------------
__global__ void zero_deg_kernel() {
    int i = blockIdx.x * blockDim.x + threadIdx.x;
    if (i < 4 * Nn) ((int*)g_deg)[i] = 0;
}

__global__ void hist_kernel(const int* __restrict__ r0, const int* __restrict__ r1,
                            const int* __restrict__ r2, const int* __restrict__ r3) {
    int i = blockIdx.x * blockDim.x + threadIdx.x;
    int et = blockIdx.y;
    if (i >= Ee) return;
    const int* r = (et == 0) ? r0 : (et == 1) ? r1 : (et == 2) ? r2 : r3;
    atomicAdd(&g_deg[et][r[i]], 1);
}

__global__ void scan_kernel() {
    // one block per edge type, 1024 threads, chunked exclusive scan over N
    const int et = blockIdx.x;
    const int t  = threadIdx.x;
    const int CH = (Nn + 1023) / 1024;   // 98
    int base = t * CH;
    int lsum = 0;
    for (int j = 0; j < CH; j++) {
        int idx = base + j;
        if (idx < Nn) lsum += g_deg[et][idx];
    }
    __shared__ int ssum[1024];
    ssum[t] = lsum;
    __syncthreads();
    for (int off = 1; off < 1024; off <<= 1) {
        int v = 0;
        if (t >= off) v = ssum[t - off];
        __syncthreads();
        ssum[t] += v;
        __syncthreads();
    }
    int run = (t == 0) ? 0 : ssum[t - 1];
    for (int j = 0; j < CH; j++) {
        int idx = base + j;
        if (idx < Nn) {
            g_rowptr[et][idx] = run;
            g_cur[et][idx]    = run;
            run += g_deg[et][idx];
        }
    }
    if (t == 1023) g_rowptr[et][Nn] = ssum[1023];
}

__global__ void scatter_kernel(const int* __restrict__ r0, const int* __restrict__ r1,
                               const int* __restrict__ r2, const int* __restrict__ r3,
                               const int* __restrict__ c0, const int* __restrict__ c1,
                               const int* __restrict__ c2, const int* __restrict__ c3,
                               const float* __restrict__ v0, const float* __restrict__ v1,
                               const float* __restrict__ v2, const float* __restrict__ v3) {
    int i = blockIdx.x * blockDim.x + threadIdx.x;
    int et = blockIdx.y;
    if (i >= Ee) return;
    const int*   r = (et == 0) ? r0 : (et == 1) ? r1 : (et == 2) ? r2 : r3;
    const int*   c = (et == 0) ? c0 : (et == 1) ? c1 : (et == 2) ? c2 : c3;
    const float* v = (et == 0) ? v0 : (et == 1) ? v1 : (et == 2) ? v2 : v3;
    int row = r[i];
    int p = atomicAdd(&g_cur[et][row], 1);
    g_cv[et][p] = make_int2(c[i], __float_as_int(v[i]));
}

// ---------------- layer-weight softmax ----------------
__global__ void wsoft_kernel(const float* __restrict__ lw) {
    int i = threadIdx.x;
    if (i < HOPS) {
        #pragma unroll
        for (int p = 0; p < 4; p += 2) {
            float a = lw[i * 4 + p], b = lw[i * 4 + p + 1];
            float m = fmaxf(a, b);
            float ea = expf(a - m), eb = expf(b - m);
            float inv = 1.0f / (ea + eb);
            g_w[i * 4 + p]     = ea * inv;
            g_w[i * 4 + p + 1] = eb * inv;
        }
    }
}

// ---------------- input projection: relu(X @ W1 + b1) -> xbuf and hbuf ----------------
__global__ void __launch_bounds__(128, 4)
proj_kernel(const float* __restrict__ X, const float* __restrict__ W,
            const float* __restrict__ b, int which /*0 paper, 1 author*/) {
    __shared__ float4 sx[32][DIN / 4];   // 32 KB
    const int tid = threadIdx.x;
    const int row0 = blockIdx.x * 32;
    const float4* X4 = (const float4*)X;
    for (int i = tid; i < 32 * (DIN / 4); i += 128) {
        int r = i / (DIN / 4), k4 = i % (DIN / 4);
        sx[r][k4] = X4[(size_t)(row0 + r) * (DIN / 4) + k4];
    }
    __syncthreads();

    const int j = tid;           // output column [0,128)
    float acc[32];
    #pragma unroll
    for (int r = 0; r < 32; r++) acc[r] = 0.0f;

    #pragma unroll 4
    for (int k4 = 0; k4 < DIN / 4; k4++) {
        float wa = W[(k4 * 4 + 0) * DH + j];
        float wb = W[(k4 * 4 + 1) * DH + j];
        float wc = W[(k4 * 4 + 2) * DH + j];
        float wd = W[(k4 * 4 + 3) * DH + j];
        #pragma unroll
        for (int r = 0; r < 32; r++) {
            float4 x = sx[r][k4];
            acc[r] += x.x * wa;
            acc[r] += x.y * wb;
            acc[r] += x.z * wc;
            acc[r] += x.w * wd;
        }
    }
    float bias = b[j];
    float* xbuf = which ? g_xa : g_xp;
    float* hbuf = which ? g_ha[0] : g_hp[0];
    #pragma unroll
    for (int r = 0; r < 32; r++) {
        float v = fmaxf(acc[r] + bias, 0.0f);
        size_t o = (size_t)(row0 + r) * DH + j;
        xbuf[o] = v;
        hbuf[o] = v;
    }
}

// ---------------- fused node-type update ----------------
// dst = w0*(spmm(et0, hA) + diag0*xs) + w1*(spmm(et1, hB) + diag1*xs)
// warp per row; lane handles float4 of features.
// (col,val) fetched cooperatively (lane i gets edge s+i, one coalesced int2 load
// per 32-edge chunk) and broadcast via shfl -> all feature gathers in a chunk
// are independent and fully overlapped.
__global__ void __launch_bounds__(256)
update_kernel(int et0, int et1,
              int selA, int selB, int selX, int selD,
              const float* __restrict__ diag0,
              const float* __restrict__ diag1,
              int widx) {
    int gw = (blockIdx.x * blockDim.x + threadIdx.x) >> 5;
    if (gw >= Nn) return;
    const int lane = threadIdx.x & 31;
    const int row = gw;

    const float4* __restrict__ hA4 = (const float4*)pick_buf(selA);
    const float4* __restrict__ hB4 = (const float4*)pick_buf(selB);
    const float4* __restrict__ xs4 = (const float4*)pick_buf(selX);
    float4* dst4 = (float4*)pick_buf(selD);

    const float w0 = g_w[widx], w1 = g_w[widx + 1];

    float4 a0 = make_float4(0.f, 0.f, 0.f, 0.f);
    float4 a1 = make_float4(0.f, 0.f, 0.f, 0.f);

    const int2* __restrict__ cv0 = g_cv[et0];
    const int2* __restrict__ cv1 = g_cv[et1];

    {
        const int s = g_rowptr[et0][row], e = g_rowptr[et0][row + 1];
        for (int base = s; base < e; base += 32) {
            const int n = min(e - base, 32);
            int2 cv = (lane < n) ? cv0[base + lane] : make_int2(0, 0);
            for (int i = 0; i < n; i++) {
                int   c = __shfl_sync(0xffffffffu, cv.x, i);
                float v = __int_as_float(__shfl_sync(0xffffffffu, cv.y, i));
                float4 h = hA4[(size_t)c * (DH / 4) + lane];
                a0.x += v * h.x; a0.y += v * h.y; a0.z += v * h.z; a0.w += v * h.w;
            }
        }
    }
    {
        const int s = g_rowptr[et1][row], e = g_rowptr[et1][row + 1];
        for (int base = s; base < e; base += 32) {
            const int n = min(e - base, 32);
            int2 cv = (lane < n) ? cv1[base + lane] : make_int2(0, 0);
            for (int i = 0; i < n; i++) {
                int   c = __shfl_sync(0xffffffffu, cv.x, i);
                float v = __int_as_float(__shfl_sync(0xffffffffu, cv.y, i));
                float4 h = hB4[(size_t)c * (DH / 4) + lane];
                a1.x += v * h.x; a1.y += v * h.y; a1.z += v * h.z; a1.w += v * h.w;
            }
        }
    }

    float4 xv = xs4[(size_t)row * (DH / 4) + lane];
    float dd = w0 * diag0[row] + w1 * diag1[row];
    float4 r;
    r.x = w0 * a0.x + w1 * a1.x + dd * xv.x;
    r.y = w0 * a0.y + w1 * a1.y + dd * xv.y;
    r.z = w0 * a0.z + w1 * a1.z + dd * xv.z;
    r.w = w0 * a0.w + w1 * a1.w + dd * xv.w;
    dst4[(size_t)row * (DH / 4) + lane] = r;
}

// ---------------- final projection: h_p @ W2 + b2 ----------------
__global__ void final_kernel(const float* __restrict__ W2, const float* __restrict__ b2,
                             float* __restrict__ out) {
    __shared__ float sW[DH * DOUT];      // 4 KB
    __shared__ float sh[32 * DH];        // 16 KB
    const int tid = threadIdx.x;
    for (int i = tid; i < DH * DOUT; i += 256) sW[i] = W2[i];
    const int row0 = blockIdx.x * 32;
    const float4* src = (const float4*)(g_hp[HOPS & 1]);
    float4* sh4 = (float4*)sh;
    for (int i = tid; i < 32 * (DH / 4); i += 256)
        sh4[i] = src[(size_t)row0 * (DH / 4) + i];
    __syncthreads();

    const int r = tid >> 3, oc = tid & 7;
    float acc = b2[oc];
    #pragma unroll 8
    for (int k = 0; k < DH; k++)
        acc += sh[r * DH + k] * sW[k * DOUT + oc];
    out[(size_t)(row0 + r) * DOUT + oc] = acc;
}

// ---------------- launch ----------------
extern "C" void kernel_launch(void* const* d_in, const int* in_sizes, int n_in,
                              void* d_out, int out_size) {
    const float* x_paper  = (const float*)d_in[0];
    const float* x_author = (const float*)d_in[1];
    const int*   rows[4];
    const int*   cols[4];
    const float* vals[4];
    const float* diag[4];
    for (int t = 0; t < 4; t++) {
        int base = 2 + t * 4;
        rows[t] = (const int*)d_in[base + 0];
        cols[t] = (const int*)d_in[base + 1];
        vals[t] = (const float*)d_in[base + 2];
        diag[t] = (const float*)d_in[base + 3];
    }
    const float* W1p = (const float*)d_in[18];
    const float* b1p = (const float*)d_in[19];
    const float* W1a = (const float*)d_in[20];
    const float* b1a = (const float*)d_in[21];
    const float* W2  = (const float*)d_in[22];
    const float* b2  = (const float*)d_in[23];
    const float* lw  = (const float*)d_in[24];
    float* out = (float*)d_out;

    // CSR build
    zero_deg_kernel<<<(4 * Nn + 255) / 256, 256>>>();
    hist_kernel<<<dim3((Ee + 255) / 256, 4), 256>>>(rows[0], rows[1], rows[2], rows[3]);
    scan_kernel<<<4, 1024>>>();
    scatter_kernel<<<dim3((Ee + 255) / 256, 4), 256>>>(
        rows[0], rows[1], rows[2], rows[3],
        cols[0], cols[1], cols[2], cols[3],
        vals[0], vals[1], vals[2], vals[3]);

    // layer weights
    wsoft_kernel<<<1, 32>>>(lw);

    // input projections (N = 3125 * 32 exactly)
    proj_kernel<<<Nn / 32, 128>>>(x_paper, W1p, b1p, 0);
    proj_kernel<<<Nn / 32, 128>>>(x_author, W1a, b1a, 1);

    // selectors: 0=g_xp 1=g_xa 2=g_hp[0] 3=g_hp[1] 4=g_ha[0] 5=g_ha[1]
    const int grid_u = (Nn * 32) / 256;   // 12500
    for (int i = 0; i < HOPS; i++) {
        int a = i & 1, bnew = (i + 1) & 1;
        // paper: pp gathers h_p[a], pa gathers h_a[a], writes h_p[bnew]
        update_kernel<<<grid_u, 256>>>(0, 1, 2 + a, 4 + a, 0, 2 + bnew,
                                       diag[0], diag[1], i * 4);
        // author: ap gathers FRESH h_p[bnew], aa gathers h_a[a], writes h_a[bnew]
        update_kernel<<<grid_u, 256>>>(2, 3, 2 + bnew, 4 + a, 1, 4 + bnew,
                                       diag[2], diag[3], i * 4 + 2);
    }

    // output projection (reads g_hp[HOPS&1] = g_hp[1])
    final_kernel<<<Nn / 32, 256>>>(W2, b2, out);
}